// round 14
// baseline (speedup 1.0000x reference)
#include <cuda_runtime.h>
#include <cuda_fp16.h>
#include <math.h>

#define H 64
#define HNUM 256
#define NMAX 100000
#define EMAX 1200000
#define NEG_SLOPE 0.2f
#define CAP 128

// ---------------- scratch (static device globals) ----------------
__device__ __half g_h[(size_t)NMAX * H];    // fp16 hidden features (layer-1 gather)
__device__ float g_out[(size_t)NMAX * H];
__device__ float4 g_xa[NMAX];               // packed {x0,x1,x2,as} per node (layer-in)
__device__ float4 g_xa2[NMAX];              // packed {agg3, as2} per node (layer-0)
__device__ float g_ad[NMAX];
__device__ float g_as[NMAX];
__device__ float g_ad2[NMAX];
__device__ int   g_deg[NMAX];               // consume-and-reset each call
__device__ int   g_st[NMAX];
__device__ int   g_en[NMAX];
__device__ int   g_cur[NMAX];
__device__ int   g_total;
__device__ int   g_ssrc[EMAX];
__device__ float g_vn[(HNUM + 1) * H];      // rows 0..255 vn_direct, row 256 vn_root
__device__ float g_vntmp[HNUM * H];
__device__ float g_uv[4 * H];
__device__ float g_wc[3 * H];               // W_in @ W_l0  (3x64)
__device__ float g_cc[H];                   // (b_in + vn_emb) @ W_l0
__device__ float g_ps[8];                   // folded l0 attention coeffs

// ---------------- setup: hist + folded params + vn init + vntmp zero + packed xa/ad ----------
__global__ void k_setup(const float* __restrict__ x,
                        const int* __restrict__ ei,
                        const float* __restrict__ w_in,
                        const float* __restrict__ a_src_in,
                        const float* __restrict__ a_dst_in,
                        const float* __restrict__ b_in,
                        const float* __restrict__ w_l,
                        const float* __restrict__ a_src_l,
                        const float* __restrict__ a_dst_l,
                        float* __restrict__ uv,
                        float* __restrict__ wc, float* __restrict__ cc,
                        float* __restrict__ ps,
                        float* __restrict__ vn, float* __restrict__ vntmp,
                        const float* __restrict__ emb,
                        float4* __restrict__ xa, float* __restrict__ ad_,
                        int* __restrict__ deg,
                        int* total, int n, int E, int nblocks_node) {
    int b = blockIdx.x, t = threadIdx.x;
    if (b == 0) {
        if (t == 0) *total = 0;
        int l = t >> 7;
        int isdst = (t >> 6) & 1;
        int j = t & 63;
        const float* a = isdst ? (a_dst_l + l * H) : (a_src_l + l * H);
        const float* W = w_l + l * H * H;
        float s = 0.f;
        #pragma unroll 8
        for (int k = 0; k < H; k++) s += W[j * H + k] * a[k];
        uv[(l * 2 + isdst) * H + j] = s;
    } else if (b == 1) {
        __shared__ float sWc[3 * H];
        __shared__ float sCc[H];
        if (t < 192) {
            int i = t >> 6, j = t & 63;
            float s = 0.f;
            #pragma unroll 8
            for (int k = 0; k < H; k++) s += w_in[i * H + k] * w_l[k * H + j];
            sWc[t] = s;
            wc[t] = s;
        } else {
            int j = t - 192;
            float s = 0.f;
            #pragma unroll 8
            for (int k = 0; k < H; k++) s += (b_in[k] + emb[k]) * w_l[k * H + j];
            sCc[j] = s;
            cc[j] = s;
        }
        __syncthreads();
        if (t < 8) {
            int isdst = t >> 2, c = t & 3;
            const float* a = isdst ? a_dst_l : a_src_l;   // layer 0
            float s = 0.f;
            if (c < 3) {
                #pragma unroll 8
                for (int m = 0; m < H; m++) s += sWc[c * H + m] * a[m];
            } else {
                #pragma unroll 8
                for (int m = 0; m < H; m++) s += sCc[m] * a[m];
            }
            ps[isdst * 4 + c] = s;
        }
    } else if (b <= 66) {
        int i = (b - 2) * 256 + t;
        if (i < (HNUM + 1) * H) vn[i] = emb[i & (H - 1)];
    } else if (b <= 130) {
        int i = (b - 67) * 256 + t;
        if (i < HNUM * H) vntmp[i] = 0.f;
    } else if (b <= 130 + nblocks_node) {
        __shared__ float swa[6];
        if (t < 6) {
            int i = t % 3;
            const float* av = (t >= 3) ? a_dst_in : a_src_in;
            float s2 = 0.f;
            #pragma unroll 8
            for (int k = 0; k < H; k++) s2 += w_in[i * H + k] * av[k];
            swa[t] = s2;
        }
        __syncthreads();
        int i = (b - 131) * 256 + t;
        if (i < n) {
            float x0 = x[3 * i], x1 = x[3 * i + 1], x2 = x[3 * i + 2];
            xa[i] = make_float4(x0, x1, x2,
                                x0 * swa[0] + x1 * swa[1] + x2 * swa[2]);
            ad_[i] = x0 * swa[3] + x1 * swa[4] + x2 * swa[5];
        }
    } else {
        int i = (b - 131 - nblocks_node) * 256 + t;
        if (i < E) atomicAdd(&deg[ei[E + i]], 1);
    }
}

// ---------------- CSR alloc + ILP-4 scatter ----------------
__global__ __launch_bounds__(256) void k_alloc(int* __restrict__ deg,
                                               int* __restrict__ st,
                                               int* __restrict__ en,
                                               int* __restrict__ cur,
                                               int* total, int n) {
    __shared__ int sWarp[8];
    __shared__ int sBase;
    int t = threadIdx.x, lane = t & 31, w = t >> 5;
    int i = blockIdx.x * 256 + t;
    int d = 0;
    if (i < n) { d = deg[i]; deg[i] = 0; }   // reset for next call; self-loop implicit
    int x = d;
    #pragma unroll
    for (int o = 1; o < 32; o <<= 1) {
        int y = __shfl_up_sync(0xffffffffu, x, o);
        if (lane >= o) x += y;
    }
    if (lane == 31) sWarp[w] = x;
    __syncthreads();
    if (t == 0) {
        int s = 0;
        #pragma unroll
        for (int k = 0; k < 8; k++) { int v = sWarp[k]; sWarp[k] = s; s += v; }
        sBase = atomicAdd(total, s);
    }
    __syncthreads();
    int start = sBase + sWarp[w] + x - d;
    if (i < n) { st[i] = start; cur[i] = start; en[i] = start + d; }
}

__global__ void k_scatter(const int* __restrict__ ei, int* cur,
                          int* __restrict__ ssrc, int E) {
    int base = blockIdx.x * 1024 + threadIdx.x;
    #pragma unroll
    for (int k = 0; k < 4; k++) {
        int i = base + k * 256;
        if (i < E) {
            int s = ei[i], d = ei[E + i];
            int pos = atomicAdd(&cur[d], 1);
            ssrc[pos] = s;
        }
    }
}

// ---------------- layer-in GAT, QUAD-PER-NODE online softmax -> xa2 pack ----------
// Aggregates raw x (one 16B load/edge); outputs xa2 = {agg3, as2} + ad2. No h write.
__global__ __launch_bounds__(256) void k_gat_in(
    const float4* __restrict__ xa,
    const float* __restrict__ ad_,
    const int* __restrict__ st, const int* __restrict__ en,
    const int* __restrict__ ssrc,
    const float* __restrict__ ps,
    float4* __restrict__ xa2, float* __restrict__ ad2, int n) {
    __shared__ float sP[8];
    int t = threadIdx.x;
    if (t < 8) sP[t] = ps[t];
    __syncthreads();
    int node = blockIdx.x * 64 + (t >> 2);
    int sub  = t & 3;
    if (node >= n) return;
    int s0 = st[node], e0 = en[node];
    float adn = ad_[node];

    float m, den, a0, a1, a2;
    if (sub == 0) {
        float4 xs = xa[node];
        float aself = xs.w + adn;
        aself = aself > 0.f ? aself : NEG_SLOPE * aself;
        m = aself; den = 1.f;
        a0 = xs.x; a1 = xs.y; a2 = xs.z;
    } else {
        m = -INFINITY; den = 0.f; a0 = a1 = a2 = 0.f;
    }

    for (int e = s0 + sub; e < e0; e += 4) {
        int s = ssrc[e];
        float4 v = xa[s];
        float a = v.w + adn;
        a = a > 0.f ? a : NEG_SLOPE * a;
        float newm = fmaxf(m, a);
        float sc = (m >= newm) ? 1.f : __expf(m - newm);
        float ex = __expf(a - newm);
        den = den * sc + ex;
        a0  = a0  * sc + ex * v.x;
        a1  = a1  * sc + ex * v.y;
        a2  = a2  * sc + ex * v.z;
        m = newm;
    }

    #pragma unroll
    for (int off = 1; off <= 2; off <<= 1) {
        float om   = __shfl_xor_sync(0xffffffffu, m,   off);
        float oden = __shfl_xor_sync(0xffffffffu, den, off);
        float oa0  = __shfl_xor_sync(0xffffffffu, a0,  off);
        float oa1  = __shfl_xor_sync(0xffffffffu, a1,  off);
        float oa2  = __shfl_xor_sync(0xffffffffu, a2,  off);
        float newm = fmaxf(m, om);
        float sc  = (m  >= newm) ? 1.f : __expf(m  - newm);
        float osc = (om >= newm) ? 1.f : __expf(om - newm);
        den = den * sc + oden * osc;
        a0  = a0  * sc + oa0  * osc;
        a1  = a1  * sc + oa1  * osc;
        a2  = a2  * sc + oa2  * osc;
        m = newm;
    }

    if (sub == 0) {
        float inv = 1.f / den;
        a0 *= inv; a1 *= inv; a2 *= inv;
        xa2[node] = make_float4(a0, a1, a2,
                                a0 * sP[0] + a1 * sP[1] + a2 * sP[2] + sP[3]);
        ad2[node] = a0 * sP[4] + a1 * sP[5] + a2 * sP[6] + sP[7];
    }
}

// ---------------- layer-0 GAT, QUAD-PER-NODE on xa2; epilogue: 3->64 affine + vntmp ----
// out_l0[node] = (sum w * agg3[src]) @ Wc + (cc + b_l0)    (weights sum to 1)
__global__ __launch_bounds__(256) void k_gat0(
    const float4* __restrict__ xa2,
    const float* __restrict__ ad2,
    const int* __restrict__ st, const int* __restrict__ en,
    const int* __restrict__ ssrc,
    const float* __restrict__ wc, const float* __restrict__ cc,
    const float* __restrict__ bias,
    const int* __restrict__ hb,
    float* __restrict__ out, float* __restrict__ vntmp, int n) {
    __shared__ float sWc[3 * H];
    __shared__ float sCcB[H];
    int t = threadIdx.x;
    if (t < 3 * H) sWc[t] = wc[t];
    if (t >= 192 && t < 192 + H) sCcB[t - 192] = cc[t - 192] + bias[t - 192];
    __syncthreads();
    int node = blockIdx.x * 64 + (t >> 2);
    int sub  = t & 3;
    if (node >= n) return;
    int s0 = st[node], e0 = en[node];
    float adn = ad2[node];

    float m, den, a0, a1, a2;
    if (sub == 0) {
        float4 xs = xa2[node];
        float aself = xs.w + adn;
        aself = aself > 0.f ? aself : NEG_SLOPE * aself;
        m = aself; den = 1.f;
        a0 = xs.x; a1 = xs.y; a2 = xs.z;
    } else {
        m = -INFINITY; den = 0.f; a0 = a1 = a2 = 0.f;
    }

    for (int e = s0 + sub; e < e0; e += 4) {
        int s = ssrc[e];
        float4 v = xa2[s];
        float a = v.w + adn;
        a = a > 0.f ? a : NEG_SLOPE * a;
        float newm = fmaxf(m, a);
        float sc = (m >= newm) ? 1.f : __expf(m - newm);
        float ex = __expf(a - newm);
        den = den * sc + ex;
        a0  = a0  * sc + ex * v.x;
        a1  = a1  * sc + ex * v.y;
        a2  = a2  * sc + ex * v.z;
        m = newm;
    }

    #pragma unroll
    for (int off = 1; off <= 2; off <<= 1) {
        float om   = __shfl_xor_sync(0xffffffffu, m,   off);
        float oden = __shfl_xor_sync(0xffffffffu, den, off);
        float oa0  = __shfl_xor_sync(0xffffffffu, a0,  off);
        float oa1  = __shfl_xor_sync(0xffffffffu, a1,  off);
        float oa2  = __shfl_xor_sync(0xffffffffu, a2,  off);
        float newm = fmaxf(m, om);
        float sc  = (m  >= newm) ? 1.f : __expf(m  - newm);
        float osc = (om >= newm) ? 1.f : __expf(om - newm);
        den = den * sc + oden * osc;
        a0  = a0  * sc + oa0  * osc;
        a1  = a1  * sc + oa1  * osc;
        a2  = a2  * sc + oa2  * osc;
        m = newm;
    }

    float inv = 1.f / den;
    a0 *= inv; a1 *= inv; a2 *= inv;

    // epilogue: 16 columns per lane; coalesced 256B/node store + vntmp atomics
    int blk = hb[node];
    int cbase = sub * 16;
    float ov[16];
    #pragma unroll
    for (int k = 0; k < 16; k++) {
        int c = cbase + k;
        ov[k] = a0 * sWc[c] + a1 * sWc[H + c] + a2 * sWc[2 * H + c] + sCcB[c];
    }
    float4* dst = (float4*)(out + (size_t)node * H + cbase);
    #pragma unroll
    for (int q = 0; q < 4; q++)
        dst[q] = make_float4(ov[q * 4], ov[q * 4 + 1], ov[q * 4 + 2], ov[q * 4 + 3]);
    #pragma unroll
    for (int k = 0; k < 16; k++)
        atomicAdd(&vntmp[blk * H + cbase + k], ov[k]);
}

// ---------------- hidden-layer GEMM: Hout(fp16) = (A + vn[hb]) @ W, plus as/ad ----------------
__global__ __launch_bounds__(256) void k_gemm64(
    const float* __restrict__ A, const float* __restrict__ W,
    const float* __restrict__ u, const float* __restrict__ v,
    const float* __restrict__ vn, const int* __restrict__ hb,
    __half* __restrict__ Hout, float* __restrict__ as_, float* __restrict__ ad_,
    int n) {
    __shared__ __align__(16) float sW[H * H];
    __shared__ float sA[64 * 65];
    int t = threadIdx.x;
    for (int i = t; i < H * H; i += 256) sW[i] = W[i];
    int block_row = blockIdx.x * 64;
    for (int i = t; i < 64 * H; i += 256) {
        int r = i >> 6, c = i & 63;
        int node = block_row + r;
        float val = 0.f;
        if (node < n) val = A[(size_t)node * H + c] + vn[hb[node] * H + c];
        sA[r * 65 + c] = val;
    }
    __syncthreads();
    int ty = t >> 4, tx = t & 15;
    float acc[4][4] = {};
    #pragma unroll 8
    for (int k = 0; k < H; k++) {
        float a0 = sA[(ty * 4 + 0) * 65 + k];
        float a1 = sA[(ty * 4 + 1) * 65 + k];
        float a2 = sA[(ty * 4 + 2) * 65 + k];
        float a3 = sA[(ty * 4 + 3) * 65 + k];
        float4 w4 = *(const float4*)&sW[k * H + tx * 4];
        acc[0][0] += a0 * w4.x; acc[0][1] += a0 * w4.y; acc[0][2] += a0 * w4.z; acc[0][3] += a0 * w4.w;
        acc[1][0] += a1 * w4.x; acc[1][1] += a1 * w4.y; acc[1][2] += a1 * w4.z; acc[1][3] += a1 * w4.w;
        acc[2][0] += a2 * w4.x; acc[2][1] += a2 * w4.y; acc[2][2] += a2 * w4.z; acc[2][3] += a2 * w4.w;
        acc[3][0] += a3 * w4.x; acc[3][1] += a3 * w4.y; acc[3][2] += a3 * w4.z; acc[3][3] += a3 * w4.w;
    }
    #pragma unroll
    for (int i = 0; i < 4; i++) {
        int node = block_row + ty * 4 + i;
        if (node < n) {
            union { uint2 u2; __half2 h2[2]; } pk;
            pk.h2[0] = __floats2half2_rn(acc[i][0], acc[i][1]);
            pk.h2[1] = __floats2half2_rn(acc[i][2], acc[i][3]);
            *(uint2*)&Hout[(size_t)node * H + tx * 4] = pk.u2;
        }
    }
    if (t < 64) {
        int node = block_row + t;
        if (node < n) {
            float s = 0.f, d = 0.f;
            #pragma unroll 8
            for (int k = 0; k < H; k++) {
                float a = sA[t * 65 + k];
                s += a * u[k];
                d += a * v[k];
            }
            as_[node] = s;
            ad_[node] = d;
        }
    }
}

// ---------------- hidden GAT: fp16 h gather, unroll-2 aggregation ----
__global__ __launch_bounds__(256) void k_gat(
    const __half2* __restrict__ h2,
    const float* __restrict__ as_, const float* __restrict__ ad_,
    const int* __restrict__ st, const int* __restrict__ en,
    const int* __restrict__ ssrc,
    const float* __restrict__ bias,
    float* __restrict__ out,
    float* __restrict__ vntmp, const int* __restrict__ hb, int n) {
    __shared__ int   s_src[8][CAP];
    __shared__ float s_w[8][CAP];
    int t = threadIdx.x, lane = t & 31, w = t >> 5;
    int node = blockIdx.x * 8 + w;
    if (node >= n) return;
    int start = st[node], end = en[node];
    int deg = end - start;
    float adn = ad_[node];
    float aself = as_[node] + adn;
    aself = aself > 0.f ? aself : NEG_SLOPE * aself;
    float2 acc;
    float den;

    if (deg <= CAP) {
        float m = aself;
        for (int i = lane; i < deg; i += 32) {
            int s = ssrc[start + i];
            float a = as_[s] + adn;
            a = a > 0.f ? a : NEG_SLOPE * a;
            s_src[w][i] = s;
            s_w[w][i] = a;
            m = fmaxf(m, a);
        }
        #pragma unroll
        for (int o = 16; o; o >>= 1) m = fmaxf(m, __shfl_xor_sync(0xffffffffu, m, o));
        float wself = __expf(aself - m);
        den = (lane == 0) ? wself : 0.f;
        {
            float2 hs = __half22float2(h2[((size_t)node << 5) + lane]);
            acc.x = wself * hs.x;
            acc.y = wself * hs.y;
        }
        for (int i = lane; i < deg; i += 32) {
            float ex = __expf(s_w[w][i] - m);
            s_w[w][i] = ex;
            den += ex;
        }
        #pragma unroll
        for (int o = 16; o; o >>= 1) den += __shfl_xor_sync(0xffffffffu, den, o);
        __syncwarp();
        float2 accB = make_float2(0.f, 0.f);
        int j = 0;
        for (; j + 1 < deg; j += 2) {
            float w0 = s_w[w][j],     w1 = s_w[w][j + 1];
            float2 v0 = __half22float2(h2[((size_t)s_src[w][j] << 5) + lane]);
            float2 v1 = __half22float2(h2[((size_t)s_src[w][j + 1] << 5) + lane]);
            acc.x  += w0 * v0.x;  acc.y  += w0 * v0.y;
            accB.x += w1 * v1.x;  accB.y += w1 * v1.y;
        }
        if (j < deg) {
            float wj = s_w[w][j];
            float2 v = __half22float2(h2[((size_t)s_src[w][j] << 5) + lane]);
            acc.x += wj * v.x;
            acc.y += wj * v.y;
        }
        acc.x += accB.x;
        acc.y += accB.y;
    } else {
        float m = aself;
        for (int e = start + lane; e < end; e += 32) {
            float a = as_[ssrc[e]] + adn;
            a = a > 0.f ? a : NEG_SLOPE * a;
            m = fmaxf(m, a);
        }
        #pragma unroll
        for (int o = 16; o; o >>= 1) m = fmaxf(m, __shfl_xor_sync(0xffffffffu, m, o));
        float wself = __expf(aself - m);
        float denl = (lane == 0) ? wself : 0.f;
        {
            float2 hs = __half22float2(h2[((size_t)node << 5) + lane]);
            acc.x = wself * hs.x;
            acc.y = wself * hs.y;
        }
        for (int eb = start; eb < end; eb += 32) {
            int e = eb + lane;
            float ex = 0.f; int s = 0;
            if (e < end) {
                s = ssrc[e];
                float a = as_[s] + adn;
                a = a > 0.f ? a : NEG_SLOPE * a;
                ex = __expf(a - m);
            }
            denl += ex;
            int cnt = min(32, end - eb);
            for (int j = 0; j < cnt; j++) {
                float wj = __shfl_sync(0xffffffffu, ex, j);
                int sj   = __shfl_sync(0xffffffffu, s, j);
                float2 v = __half22float2(h2[((size_t)sj << 5) + lane]);
                acc.x += wj * v.x;
                acc.y += wj * v.y;
            }
        }
        den = denl;
        #pragma unroll
        for (int o = 16; o; o >>= 1) den += __shfl_xor_sync(0xffffffffu, den, o);
    }

    float inv = 1.f / den;
    float2 b = ((const float2*)bias)[lane];
    float2 o2 = make_float2(acc.x * inv + b.x, acc.y * inv + b.y);
    ((float2*)out)[(size_t)node * 32 + lane] = o2;
    if (vntmp) {
        int blk = hb[node];
        atomicAdd(&vntmp[blk * H + lane * 2],     o2.x);
        atomicAdd(&vntmp[blk * H + lane * 2 + 1], o2.y);
    }
}

// ---------------- fused vn update + both MLPs ----------------
__global__ __launch_bounds__(256) void k_vn_mlp2(
    float* vn, const float* __restrict__ vn_tmp,
    const float* __restrict__ mw1, const float* __restrict__ mb1,
    const float* __restrict__ mw2, const float* __restrict__ mb2, int rows) {
    __shared__ __align__(16) float sW[H * H];
    __shared__ float sV[64 * 65];
    __shared__ float sRoot[H];
    __shared__ float sColNew[H];
    __shared__ float red[4][H];
    int t = threadIdx.x;
    int r0 = blockIdx.x * 64;

    if (t < H) sRoot[t] = vn[HNUM * H + t];
    __syncthreads();
    {
        int c = t & 63, g = t >> 6;
        float s = 0.f;
        for (int r = g; r < HNUM; r += 4) s += vn[r * H + c] + vn_tmp[r * H + c];
        red[g][c] = s;
    }
    __syncthreads();
    if (t < H) sColNew[t] = red[0][t] + red[1][t] + red[2][t] + red[3][t] + 257.f * sRoot[t];
    __syncthreads();
    for (int i = t; i < 64 * H; i += 256) {
        int r = i >> 6, c = i & 63;
        int gr = r0 + r;
        float val = 0.f;
        if (gr < HNUM)      val = vn[gr * H + c] + vn_tmp[gr * H + c] + sRoot[c];
        else if (gr == HNUM) val = sColNew[c];
        sV[r * 65 + c] = val;
    }
    int ty = t >> 4, tx = t & 15;
    for (int m = 0; m < 2; m++) {
        const float* w1 = mw1 + m * H * H;
        const float* b1 = mb1 + m * H;
        const float* w2 = mw2 + m * H * H;
        const float* b2 = mb2 + m * H;
        for (int i = t; i < H * H; i += 256) sW[i] = w1[i];
        __syncthreads();
        float acc[4][4] = {};
        #pragma unroll 8
        for (int k = 0; k < H; k++) {
            float a0 = sV[(ty * 4 + 0) * 65 + k];
            float a1 = sV[(ty * 4 + 1) * 65 + k];
            float a2 = sV[(ty * 4 + 2) * 65 + k];
            float a3 = sV[(ty * 4 + 3) * 65 + k];
            float4 w4 = *(const float4*)&sW[k * H + tx * 4];
            acc[0][0] += a0 * w4.x; acc[0][1] += a0 * w4.y; acc[0][2] += a0 * w4.z; acc[0][3] += a0 * w4.w;
            acc[1][0] += a1 * w4.x; acc[1][1] += a1 * w4.y; acc[1][2] += a1 * w4.z; acc[1][3] += a1 * w4.w;
            acc[2][0] += a2 * w4.x; acc[2][1] += a2 * w4.y; acc[2][2] += a2 * w4.z; acc[2][3] += a2 * w4.w;
            acc[3][0] += a3 * w4.x; acc[3][1] += a3 * w4.y; acc[3][2] += a3 * w4.z; acc[3][3] += a3 * w4.w;
        }
        __syncthreads();
        #pragma unroll
        for (int i = 0; i < 4; i++)
            #pragma unroll
            for (int j = 0; j < 4; j++) {
                float vbl = acc[i][j] + b1[tx * 4 + j];
                sV[(ty * 4 + i) * 65 + tx * 4 + j] = vbl > 0.f ? vbl : 0.f;
            }
        for (int i = t; i < H * H; i += 256) sW[i] = w2[i];
        __syncthreads();
        float acc2[4][4] = {};
        #pragma unroll 8
        for (int k = 0; k < H; k++) {
            float a0 = sV[(ty * 4 + 0) * 65 + k];
            float a1 = sV[(ty * 4 + 1) * 65 + k];
            float a2 = sV[(ty * 4 + 2) * 65 + k];
            float a3 = sV[(ty * 4 + 3) * 65 + k];
            float4 w4 = *(const float4*)&sW[k * H + tx * 4];
            acc2[0][0] += a0 * w4.x; acc2[0][1] += a0 * w4.y; acc2[0][2] += a0 * w4.z; acc2[0][3] += a0 * w4.w;
            acc2[1][0] += a1 * w4.x; acc2[1][1] += a1 * w4.y; acc2[1][2] += a1 * w4.z; acc2[1][3] += a1 * w4.w;
            acc2[2][0] += a2 * w4.x; acc2[2][1] += a2 * w4.y; acc2[2][2] += a2 * w4.z; acc2[2][3] += a2 * w4.w;
            acc2[3][0] += a3 * w4.x; acc2[3][1] += a3 * w4.y; acc2[3][2] += a3 * w4.z; acc2[3][3] += a3 * w4.w;
        }
        __syncthreads();
        #pragma unroll
        for (int i = 0; i < 4; i++)
            #pragma unroll
            for (int j = 0; j < 4; j++) {
                float vbl = acc2[i][j] + b2[tx * 4 + j];
                sV[(ty * 4 + i) * 65 + tx * 4 + j] = vbl > 0.f ? vbl : 0.f;
            }
        __syncthreads();
    }
    for (int i = t; i < 64 * H; i += 256) {
        int r = i >> 6, c = i & 63;
        if (r0 + r < rows) vn[(r0 + r) * H + c] = sV[r * 65 + c];
    }
}

// ---------------- host launch ----------------
extern "C" void kernel_launch(void* const* d_in, const int* in_sizes, int n_in,
                              void* d_out, int out_size) {
    const float* x  = (const float*)d_in[0];
    const int*   ei = (const int*)d_in[1];
    const int*   hb = (const int*)d_in[2];
    int base = (n_in >= 18) ? 5 : 4;
    const float* w_in     = (const float*)d_in[base + 0];
    const float* a_src_in = (const float*)d_in[base + 1];
    const float* a_dst_in = (const float*)d_in[base + 2];
    const float* b_in     = (const float*)d_in[base + 3];
    const float* w_l      = (const float*)d_in[base + 4];
    const float* a_src_l  = (const float*)d_in[base + 5];
    const float* a_dst_l  = (const float*)d_in[base + 6];
    const float* b_l      = (const float*)d_in[base + 7];
    const float* mw1      = (const float*)d_in[base + 8];
    const float* mb1      = (const float*)d_in[base + 9];
    const float* mw2      = (const float*)d_in[base + 10];
    const float* mb2      = (const float*)d_in[base + 11];
    const float* vne      = (const float*)d_in[base + 12];

    int N = in_sizes[0] / 3;
    int E = in_sizes[1] / 2;

    float *pout, *pas, *pad, *pad2, *pvn, *pvntmp, *puv, *pwc, *pcc, *pps;
    float4 *pxa, *pxa2;
    __half* ph;
    int *pdeg, *pst, *pen, *pcur, *pssrc, *ptotal;
    cudaGetSymbolAddress((void**)&ph, g_h);
    cudaGetSymbolAddress((void**)&pout, g_out);
    cudaGetSymbolAddress((void**)&pxa, g_xa);
    cudaGetSymbolAddress((void**)&pxa2, g_xa2);
    cudaGetSymbolAddress((void**)&pas, g_as);
    cudaGetSymbolAddress((void**)&pad, g_ad);
    cudaGetSymbolAddress((void**)&pad2, g_ad2);
    cudaGetSymbolAddress((void**)&pdeg, g_deg);
    cudaGetSymbolAddress((void**)&pst, g_st);
    cudaGetSymbolAddress((void**)&pen, g_en);
    cudaGetSymbolAddress((void**)&pcur, g_cur);
    cudaGetSymbolAddress((void**)&pssrc, g_ssrc);
    cudaGetSymbolAddress((void**)&ptotal, g_total);
    cudaGetSymbolAddress((void**)&pvn, g_vn);
    cudaGetSymbolAddress((void**)&pvntmp, g_vntmp);
    cudaGetSymbolAddress((void**)&puv, g_uv);
    cudaGetSymbolAddress((void**)&pwc, g_wc);
    cudaGetSymbolAddress((void**)&pcc, g_cc);
    cudaGetSymbolAddress((void**)&pps, g_ps);

    int nwarp_blocks = (N + 7) / 8;
    int gemm_blocks  = (N + 63) / 64;
    int quad_blocks  = (N + 63) / 64;
    int nblocks_node = (N + 255) / 256;
    int nblocks_edge = (E + 255) / 256;
    int setup_blocks = 131 + nblocks_node + nblocks_edge;

    // 0: setup
    k_setup<<<setup_blocks, 256>>>(x, ei, w_in, a_src_in, a_dst_in, b_in,
                                   w_l, a_src_l, a_dst_l,
                                   puv, pwc, pcc, pps,
                                   pvn, pvntmp, vne, pxa, pad, pdeg,
                                   ptotal, N, E, nblocks_node);
    // 1-2: CSR alloc + scatter
    k_alloc<<<nblocks_node, 256>>>(pdeg, pst, pen, pcur, ptotal, N);
    k_scatter<<<(E + 1023) / 1024, 256>>>(ei, pcur, pssrc, E);

    // 3: layer-in GAT -> xa2 pack (no h materialization)
    k_gat_in<<<quad_blocks, 256>>>(pxa, pad, pst, pen, pssrc,
                                   pps, pxa2, pad2, N);
    // 4: layer-0 GAT on xa2 -> out (fp32) + vntmp
    k_gat0<<<quad_blocks, 256>>>(pxa2, pad2, pst, pen, pssrc,
                                 pwc, pcc, b_l, hb, pout, pvntmp, N);
    // 5: fused vn update + both MLPs
    k_vn_mlp2<<<(HNUM + 1 + 63) / 64, 256>>>(pvn, pvntmp, mw1, mb1, mw2, mb2, HNUM + 1);

    // 6-7: l = 1 (trailing vn updates are dead code w.r.t. output)
    k_gemm64<<<gemm_blocks, 256>>>(pout, w_l + H * H, puv + 2 * H, puv + 3 * H,
                                   pvn, hb, ph, pas, pad, N);
    k_gat<<<nwarp_blocks, 256>>>((const __half2*)ph, pas, pad, pst, pen, pssrc,
                                 b_l + H, (float*)d_out, nullptr, nullptr, N);
}

// round 15
// speedup vs baseline: 1.2425x; 1.2425x over previous
#include <cuda_runtime.h>
#include <cuda_fp16.h>
#include <math.h>

#define H 64
#define HNUM 256
#define NMAX 100000
#define EMAX 1200000
#define NEG_SLOPE 0.2f
#define CAP 128

// ---------------- scratch (static device globals) ----------------
__device__ __half g_h[(size_t)NMAX * H];    // fp16 hidden features (layer-1 gather)
__device__ float4 g_xa[NMAX];               // packed {x0,x1,x2,as} per node (layer-in)
__device__ float4 g_xa2[NMAX];              // packed {agg3, as2} per node (layer-0 input)
__device__ float4 g_xa3[NMAX];              // packed {agg3_l0, -} per node (layer-0 output)
__device__ float g_ad[NMAX];
__device__ float g_as[NMAX];
__device__ float g_ad2[NMAX];
__device__ int   g_deg[NMAX];               // consume-and-reset each call
__device__ int   g_st[NMAX];
__device__ int   g_en[NMAX];
__device__ int   g_cur[NMAX];
__device__ int   g_total;
__device__ int   g_ssrc[EMAX];
__device__ float g_vn[(HNUM + 1) * H];      // rows 0..255 vn_direct, row 256 vn_root
__device__ float g_vnagg[HNUM * 4];         // per-block {sum agg3, count}
__device__ float g_uv[4 * H];
__device__ float g_wc[3 * H];               // W_in @ W_l0  (3x64)
__device__ float g_cc[H];                   // (b_in + vn_emb) @ W_l0
__device__ float g_ps[8];                   // folded l0 attention coeffs

// ---------------- setup: hist + folded params + vn init + vnagg zero + packed xa/ad ----------
__global__ void k_setup(const float* __restrict__ x,
                        const int* __restrict__ ei,
                        const float* __restrict__ w_in,
                        const float* __restrict__ a_src_in,
                        const float* __restrict__ a_dst_in,
                        const float* __restrict__ b_in,
                        const float* __restrict__ w_l,
                        const float* __restrict__ a_src_l,
                        const float* __restrict__ a_dst_l,
                        float* __restrict__ uv,
                        float* __restrict__ wc, float* __restrict__ cc,
                        float* __restrict__ ps,
                        float* __restrict__ vn, float* __restrict__ vnagg,
                        const float* __restrict__ emb,
                        float4* __restrict__ xa, float* __restrict__ ad_,
                        int* __restrict__ deg,
                        int* total, int n, int E, int nblocks_node) {
    int b = blockIdx.x, t = threadIdx.x;
    if (b == 0) {
        if (t == 0) *total = 0;
        int l = t >> 7;
        int isdst = (t >> 6) & 1;
        int j = t & 63;
        const float* a = isdst ? (a_dst_l + l * H) : (a_src_l + l * H);
        const float* W = w_l + l * H * H;
        float s = 0.f;
        #pragma unroll 8
        for (int k = 0; k < H; k++) s += W[j * H + k] * a[k];
        uv[(l * 2 + isdst) * H + j] = s;
    } else if (b == 1) {
        __shared__ float sWc[3 * H];
        __shared__ float sCc[H];
        if (t < 192) {
            int i = t >> 6, j = t & 63;
            float s = 0.f;
            #pragma unroll 8
            for (int k = 0; k < H; k++) s += w_in[i * H + k] * w_l[k * H + j];
            sWc[t] = s;
            wc[t] = s;
        } else {
            int j = t - 192;
            float s = 0.f;
            #pragma unroll 8
            for (int k = 0; k < H; k++) s += (b_in[k] + emb[k]) * w_l[k * H + j];
            sCc[j] = s;
            cc[j] = s;
        }
        __syncthreads();
        if (t < 8) {
            int isdst = t >> 2, c = t & 3;
            const float* a = isdst ? a_dst_l : a_src_l;   // layer 0
            float s = 0.f;
            if (c < 3) {
                #pragma unroll 8
                for (int m = 0; m < H; m++) s += sWc[c * H + m] * a[m];
            } else {
                #pragma unroll 8
                for (int m = 0; m < H; m++) s += sCc[m] * a[m];
            }
            ps[isdst * 4 + c] = s;
        }
    } else if (b <= 66) {
        int i = (b - 2) * 256 + t;
        if (i < (HNUM + 1) * H) vn[i] = emb[i & (H - 1)];
    } else if (b <= 70) {
        int i = (b - 67) * 256 + t;
        if (i < HNUM * 4) vnagg[i] = 0.f;
    } else if (b <= 70 + nblocks_node) {
        __shared__ float swa[6];
        if (t < 6) {
            int i = t % 3;
            const float* av = (t >= 3) ? a_dst_in : a_src_in;
            float s2 = 0.f;
            #pragma unroll 8
            for (int k = 0; k < H; k++) s2 += w_in[i * H + k] * av[k];
            swa[t] = s2;
        }
        __syncthreads();
        int i = (b - 71) * 256 + t;
        if (i < n) {
            float x0 = x[3 * i], x1 = x[3 * i + 1], x2 = x[3 * i + 2];
            xa[i] = make_float4(x0, x1, x2,
                                x0 * swa[0] + x1 * swa[1] + x2 * swa[2]);
            ad_[i] = x0 * swa[3] + x1 * swa[4] + x2 * swa[5];
        }
    } else {
        int i = (b - 71 - nblocks_node) * 256 + t;
        if (i < E) atomicAdd(&deg[ei[E + i]], 1);
    }
}

// ---------------- CSR alloc + ILP-4 scatter ----------------
__global__ __launch_bounds__(256) void k_alloc(int* __restrict__ deg,
                                               int* __restrict__ st,
                                               int* __restrict__ en,
                                               int* __restrict__ cur,
                                               int* total, int n) {
    __shared__ int sWarp[8];
    __shared__ int sBase;
    int t = threadIdx.x, lane = t & 31, w = t >> 5;
    int i = blockIdx.x * 256 + t;
    int d = 0;
    if (i < n) { d = deg[i]; deg[i] = 0; }
    int x = d;
    #pragma unroll
    for (int o = 1; o < 32; o <<= 1) {
        int y = __shfl_up_sync(0xffffffffu, x, o);
        if (lane >= o) x += y;
    }
    if (lane == 31) sWarp[w] = x;
    __syncthreads();
    if (t == 0) {
        int s = 0;
        #pragma unroll
        for (int k = 0; k < 8; k++) { int v = sWarp[k]; sWarp[k] = s; s += v; }
        sBase = atomicAdd(total, s);
    }
    __syncthreads();
    int start = sBase + sWarp[w] + x - d;
    if (i < n) { st[i] = start; cur[i] = start; en[i] = start + d; }
}

__global__ void k_scatter(const int* __restrict__ ei, int* cur,
                          int* __restrict__ ssrc, int E) {
    int base = blockIdx.x * 1024 + threadIdx.x;
    #pragma unroll
    for (int k = 0; k < 4; k++) {
        int i = base + k * 256;
        if (i < E) {
            int s = ei[i], d = ei[E + i];
            int pos = atomicAdd(&cur[d], 1);
            ssrc[pos] = s;
        }
    }
}

// ---------------- layer-in GAT, QUAD-PER-NODE online softmax -> xa2 pack ----------
__global__ __launch_bounds__(256) void k_gat_in(
    const float4* __restrict__ xa,
    const float* __restrict__ ad_,
    const int* __restrict__ st, const int* __restrict__ en,
    const int* __restrict__ ssrc,
    const float* __restrict__ ps,
    float4* __restrict__ xa2, float* __restrict__ ad2, int n) {
    __shared__ float sP[8];
    int t = threadIdx.x;
    if (t < 8) sP[t] = ps[t];
    __syncthreads();
    int node = blockIdx.x * 64 + (t >> 2);
    int sub  = t & 3;
    if (node >= n) return;
    int s0 = st[node], e0 = en[node];
    float adn = ad_[node];

    float m, den, a0, a1, a2;
    if (sub == 0) {
        float4 xs = xa[node];
        float aself = xs.w + adn;
        aself = aself > 0.f ? aself : NEG_SLOPE * aself;
        m = aself; den = 1.f;
        a0 = xs.x; a1 = xs.y; a2 = xs.z;
    } else {
        m = -INFINITY; den = 0.f; a0 = a1 = a2 = 0.f;
    }

    for (int e = s0 + sub; e < e0; e += 4) {
        int s = ssrc[e];
        float4 v = xa[s];
        float a = v.w + adn;
        a = a > 0.f ? a : NEG_SLOPE * a;
        float newm = fmaxf(m, a);
        float sc = (m >= newm) ? 1.f : __expf(m - newm);
        float ex = __expf(a - newm);
        den = den * sc + ex;
        a0  = a0  * sc + ex * v.x;
        a1  = a1  * sc + ex * v.y;
        a2  = a2  * sc + ex * v.z;
        m = newm;
    }

    #pragma unroll
    for (int off = 1; off <= 2; off <<= 1) {
        float om   = __shfl_xor_sync(0xffffffffu, m,   off);
        float oden = __shfl_xor_sync(0xffffffffu, den, off);
        float oa0  = __shfl_xor_sync(0xffffffffu, a0,  off);
        float oa1  = __shfl_xor_sync(0xffffffffu, a1,  off);
        float oa2  = __shfl_xor_sync(0xffffffffu, a2,  off);
        float newm = fmaxf(m, om);
        float sc  = (m  >= newm) ? 1.f : __expf(m  - newm);
        float osc = (om >= newm) ? 1.f : __expf(om - newm);
        den = den * sc + oden * osc;
        a0  = a0  * sc + oa0  * osc;
        a1  = a1  * sc + oa1  * osc;
        a2  = a2  * sc + oa2  * osc;
        m = newm;
    }

    if (sub == 0) {
        float inv = 1.f / den;
        a0 *= inv; a1 *= inv; a2 *= inv;
        xa2[node] = make_float4(a0, a1, a2,
                                a0 * sP[0] + a1 * sP[1] + a2 * sP[2] + sP[3]);
        ad2[node] = a0 * sP[4] + a1 * sP[5] + a2 * sP[6] + sP[7];
    }
}

// ---------------- layer-0 GAT, QUAD-PER-NODE on xa2 -> xa3 pack + rank-3 vnagg ----------
__global__ __launch_bounds__(256) void k_gat0(
    const float4* __restrict__ xa2,
    const float* __restrict__ ad2,
    const int* __restrict__ st, const int* __restrict__ en,
    const int* __restrict__ ssrc,
    const int* __restrict__ hb,
    float4* __restrict__ xa3, float* __restrict__ vnagg, int n) {
    int t = threadIdx.x;
    int node = blockIdx.x * 64 + (t >> 2);
    int sub  = t & 3;
    if (node >= n) return;
    int s0 = st[node], e0 = en[node];
    float adn = ad2[node];

    float m, den, a0, a1, a2;
    if (sub == 0) {
        float4 xs = xa2[node];
        float aself = xs.w + adn;
        aself = aself > 0.f ? aself : NEG_SLOPE * aself;
        m = aself; den = 1.f;
        a0 = xs.x; a1 = xs.y; a2 = xs.z;
    } else {
        m = -INFINITY; den = 0.f; a0 = a1 = a2 = 0.f;
    }

    for (int e = s0 + sub; e < e0; e += 4) {
        int s = ssrc[e];
        float4 v = xa2[s];
        float a = v.w + adn;
        a = a > 0.f ? a : NEG_SLOPE * a;
        float newm = fmaxf(m, a);
        float sc = (m >= newm) ? 1.f : __expf(m - newm);
        float ex = __expf(a - newm);
        den = den * sc + ex;
        a0  = a0  * sc + ex * v.x;
        a1  = a1  * sc + ex * v.y;
        a2  = a2  * sc + ex * v.z;
        m = newm;
    }

    #pragma unroll
    for (int off = 1; off <= 2; off <<= 1) {
        float om   = __shfl_xor_sync(0xffffffffu, m,   off);
        float oden = __shfl_xor_sync(0xffffffffu, den, off);
        float oa0  = __shfl_xor_sync(0xffffffffu, a0,  off);
        float oa1  = __shfl_xor_sync(0xffffffffu, a1,  off);
        float oa2  = __shfl_xor_sync(0xffffffffu, a2,  off);
        float newm = fmaxf(m, om);
        float sc  = (m  >= newm) ? 1.f : __expf(m  - newm);
        float osc = (om >= newm) ? 1.f : __expf(om - newm);
        den = den * sc + oden * osc;
        a0  = a0  * sc + oa0  * osc;
        a1  = a1  * sc + oa1  * osc;
        a2  = a2  * sc + oa2  * osc;
        m = newm;
    }

    if (sub == 0) {
        float inv = 1.f / den;
        a0 *= inv; a1 *= inv; a2 *= inv;
        xa3[node] = make_float4(a0, a1, a2, 0.f);
        int blk = hb[node];
        atomicAdd(&vnagg[blk * 4 + 0], a0);
        atomicAdd(&vnagg[blk * 4 + 1], a1);
        atomicAdd(&vnagg[blk * 4 + 2], a2);
        atomicAdd(&vnagg[blk * 4 + 3], 1.f);
    }
}

// ---------------- hidden-layer GEMM: reconstruct A from rank-3 + vn, emit h fp16 + as/ad ----
__global__ __launch_bounds__(256) void k_gemm64(
    const float4* __restrict__ xa3,
    const float* __restrict__ wc, const float* __restrict__ cc,
    const float* __restrict__ bias0,
    const float* __restrict__ W,
    const float* __restrict__ u, const float* __restrict__ v,
    const float* __restrict__ vn, const int* __restrict__ hb,
    __half* __restrict__ Hout, float* __restrict__ as_, float* __restrict__ ad_,
    int n) {
    __shared__ __align__(16) float sW[H * H];
    __shared__ float sA[64 * 65];
    __shared__ float sWc[3 * H];
    __shared__ float sCcB[H];
    __shared__ float sAg[64 * 4];
    __shared__ int   sHb[64];
    int t = threadIdx.x;
    for (int i = t; i < H * H; i += 256) sW[i] = W[i];
    if (t < 192) sWc[t] = wc[t];
    if (t >= 192 && t < 256) sCcB[t - 192] = cc[t - 192] + bias0[t - 192];
    int block_row = blockIdx.x * 64;
    if (t < 64) {
        int node = block_row + t;
        if (node < n) {
            float4 g = xa3[node];
            sAg[t * 4] = g.x; sAg[t * 4 + 1] = g.y; sAg[t * 4 + 2] = g.z; sAg[t * 4 + 3] = 0.f;
            sHb[t] = hb[node];
        } else {
            sAg[t * 4] = sAg[t * 4 + 1] = sAg[t * 4 + 2] = sAg[t * 4 + 3] = 0.f;
            sHb[t] = 0;
        }
    }
    __syncthreads();
    for (int i = t; i < 64 * H; i += 256) {
        int r = i >> 6, c = i & 63;
        int node = block_row + r;
        float val = 0.f;
        if (node < n)
            val = sAg[r * 4] * sWc[c] + sAg[r * 4 + 1] * sWc[H + c]
                + sAg[r * 4 + 2] * sWc[2 * H + c] + sCcB[c] + vn[sHb[r] * H + c];
        sA[r * 65 + c] = val;
    }
    __syncthreads();
    int ty = t >> 4, tx = t & 15;
    float acc[4][4] = {};
    #pragma unroll 8
    for (int k = 0; k < H; k++) {
        float a0 = sA[(ty * 4 + 0) * 65 + k];
        float a1 = sA[(ty * 4 + 1) * 65 + k];
        float a2 = sA[(ty * 4 + 2) * 65 + k];
        float a3 = sA[(ty * 4 + 3) * 65 + k];
        float4 w4 = *(const float4*)&sW[k * H + tx * 4];
        acc[0][0] += a0 * w4.x; acc[0][1] += a0 * w4.y; acc[0][2] += a0 * w4.z; acc[0][3] += a0 * w4.w;
        acc[1][0] += a1 * w4.x; acc[1][1] += a1 * w4.y; acc[1][2] += a1 * w4.z; acc[1][3] += a1 * w4.w;
        acc[2][0] += a2 * w4.x; acc[2][1] += a2 * w4.y; acc[2][2] += a2 * w4.z; acc[2][3] += a2 * w4.w;
        acc[3][0] += a3 * w4.x; acc[3][1] += a3 * w4.y; acc[3][2] += a3 * w4.z; acc[3][3] += a3 * w4.w;
    }
    #pragma unroll
    for (int i = 0; i < 4; i++) {
        int node = block_row + ty * 4 + i;
        if (node < n) {
            union { uint2 u2; __half2 h2[2]; } pk;
            pk.h2[0] = __floats2half2_rn(acc[i][0], acc[i][1]);
            pk.h2[1] = __floats2half2_rn(acc[i][2], acc[i][3]);
            *(uint2*)&Hout[(size_t)node * H + tx * 4] = pk.u2;
        }
    }
    if (t < 64) {
        int node = block_row + t;
        if (node < n) {
            float s = 0.f, d = 0.f;
            #pragma unroll 8
            for (int k = 0; k < H; k++) {
                float a = sA[t * 65 + k];
                s += a * u[k];
                d += a * v[k];
            }
            as_[node] = s;
            ad_[node] = d;
        }
    }
}

// ---------------- hidden GAT (layer 1): fp16 h gather, unroll-2 aggregation ----
__global__ __launch_bounds__(256) void k_gat(
    const __half2* __restrict__ h2,
    const float* __restrict__ as_, const float* __restrict__ ad_,
    const int* __restrict__ st, const int* __restrict__ en,
    const int* __restrict__ ssrc,
    const float* __restrict__ bias,
    float* __restrict__ out, int n) {
    __shared__ int   s_src[8][CAP];
    __shared__ float s_w[8][CAP];
    int t = threadIdx.x, lane = t & 31, w = t >> 5;
    int node = blockIdx.x * 8 + w;
    if (node >= n) return;
    int start = st[node], end = en[node];
    int deg = end - start;
    float adn = ad_[node];
    float aself = as_[node] + adn;
    aself = aself > 0.f ? aself : NEG_SLOPE * aself;
    float2 acc;
    float den;

    if (deg <= CAP) {
        float m = aself;
        for (int i = lane; i < deg; i += 32) {
            int s = ssrc[start + i];
            float a = as_[s] + adn;
            a = a > 0.f ? a : NEG_SLOPE * a;
            s_src[w][i] = s;
            s_w[w][i] = a;
            m = fmaxf(m, a);
        }
        #pragma unroll
        for (int o = 16; o; o >>= 1) m = fmaxf(m, __shfl_xor_sync(0xffffffffu, m, o));
        float wself = __expf(aself - m);
        den = (lane == 0) ? wself : 0.f;
        {
            float2 hs = __half22float2(h2[((size_t)node << 5) + lane]);
            acc.x = wself * hs.x;
            acc.y = wself * hs.y;
        }
        for (int i = lane; i < deg; i += 32) {
            float ex = __expf(s_w[w][i] - m);
            s_w[w][i] = ex;
            den += ex;
        }
        #pragma unroll
        for (int o = 16; o; o >>= 1) den += __shfl_xor_sync(0xffffffffu, den, o);
        __syncwarp();
        float2 accB = make_float2(0.f, 0.f);
        int j = 0;
        for (; j + 1 < deg; j += 2) {
            float w0 = s_w[w][j],     w1 = s_w[w][j + 1];
            float2 v0 = __half22float2(h2[((size_t)s_src[w][j] << 5) + lane]);
            float2 v1 = __half22float2(h2[((size_t)s_src[w][j + 1] << 5) + lane]);
            acc.x  += w0 * v0.x;  acc.y  += w0 * v0.y;
            accB.x += w1 * v1.x;  accB.y += w1 * v1.y;
        }
        if (j < deg) {
            float wj = s_w[w][j];
            float2 v = __half22float2(h2[((size_t)s_src[w][j] << 5) + lane]);
            acc.x += wj * v.x;
            acc.y += wj * v.y;
        }
        acc.x += accB.x;
        acc.y += accB.y;
    } else {
        float m = aself;
        for (int e = start + lane; e < end; e += 32) {
            float a = as_[ssrc[e]] + adn;
            a = a > 0.f ? a : NEG_SLOPE * a;
            m = fmaxf(m, a);
        }
        #pragma unroll
        for (int o = 16; o; o >>= 1) m = fmaxf(m, __shfl_xor_sync(0xffffffffu, m, o));
        float wself = __expf(aself - m);
        float denl = (lane == 0) ? wself : 0.f;
        {
            float2 hs = __half22float2(h2[((size_t)node << 5) + lane]);
            acc.x = wself * hs.x;
            acc.y = wself * hs.y;
        }
        for (int eb = start; eb < end; eb += 32) {
            int e = eb + lane;
            float ex = 0.f; int s = 0;
            if (e < end) {
                s = ssrc[e];
                float a = as_[s] + adn;
                a = a > 0.f ? a : NEG_SLOPE * a;
                ex = __expf(a - m);
            }
            denl += ex;
            int cnt = min(32, end - eb);
            for (int j = 0; j < cnt; j++) {
                float wj = __shfl_sync(0xffffffffu, ex, j);
                int sj   = __shfl_sync(0xffffffffu, s, j);
                float2 v = __half22float2(h2[((size_t)sj << 5) + lane]);
                acc.x += wj * v.x;
                acc.y += wj * v.y;
            }
        }
        den = denl;
        #pragma unroll
        for (int o = 16; o; o >>= 1) den += __shfl_xor_sync(0xffffffffu, den, o);
    }

    float inv = 1.f / den;
    float2 b = ((const float2*)bias)[lane];
    float2 o2 = make_float2(acc.x * inv + b.x, acc.y * inv + b.y);
    ((float2*)out)[(size_t)node * 32 + lane] = o2;
}

// ---------------- fused vn update (rank-3 expansion) + both MLPs ----------------
__global__ __launch_bounds__(256) void k_vn_mlp2(
    float* vn, const float* __restrict__ vnagg,
    const float* __restrict__ wc, const float* __restrict__ cc,
    const float* __restrict__ bias0,
    const float* __restrict__ mw1, const float* __restrict__ mb1,
    const float* __restrict__ mw2, const float* __restrict__ mb2, int rows) {
    __shared__ __align__(16) float sW[H * H];
    __shared__ float sV[64 * 65];
    __shared__ float sRoot[H];
    __shared__ float sColNew[H];
    __shared__ float red[4][H];
    __shared__ float sWc[3 * H];
    __shared__ float sCcB[H];
    __shared__ float sAg[64 * 4];
    int t = threadIdx.x;
    int r0 = blockIdx.x * 64;

    if (t < H) sRoot[t] = vn[HNUM * H + t];
    if (t < 192) sWc[t] = wc[t];
    if (t >= 192 && t < 256) sCcB[t - 192] = cc[t - 192] + bias0[t - 192];
    {
        int idx = r0 * 4 + t;   // 64 rows * 4 = 256 values for this block's rows
        sAg[t] = (idx < HNUM * 4) ? vnagg[idx] : 0.f;
    }
    __syncthreads();
    // colsum over all 256 direct rows of (vn + rec); rec = agg@Wc + cnt*ccb
    {
        int c = t & 63, g = t >> 6;
        float svn = 0.f, s0 = 0.f, s1 = 0.f, s2 = 0.f, s3 = 0.f;
        for (int r = g; r < HNUM; r += 4) {
            svn += vn[r * H + c];
            s0 += vnagg[r * 4];
            s1 += vnagg[r * 4 + 1];
            s2 += vnagg[r * 4 + 2];
            s3 += vnagg[r * 4 + 3];
        }
        red[g][c] = svn + s0 * sWc[c] + s1 * sWc[H + c] + s2 * sWc[2 * H + c] + s3 * sCcB[c];
    }
    __syncthreads();
    if (t < H) sColNew[t] = red[0][t] + red[1][t] + red[2][t] + red[3][t] + 257.f * sRoot[t];
    __syncthreads();
    for (int i = t; i < 64 * H; i += 256) {
        int r = i >> 6, c = i & 63;
        int gr = r0 + r;
        float val = 0.f;
        if (gr < HNUM) {
            float rec = sAg[r * 4] * sWc[c] + sAg[r * 4 + 1] * sWc[H + c]
                      + sAg[r * 4 + 2] * sWc[2 * H + c] + sAg[r * 4 + 3] * sCcB[c];
            val = vn[gr * H + c] + rec + sRoot[c];
        } else if (gr == HNUM) val = sColNew[c];
        sV[r * 65 + c] = val;
    }
    int ty = t >> 4, tx = t & 15;
    for (int m = 0; m < 2; m++) {
        const float* w1 = mw1 + m * H * H;
        const float* b1 = mb1 + m * H;
        const float* w2 = mw2 + m * H * H;
        const float* b2 = mb2 + m * H;
        for (int i = t; i < H * H; i += 256) sW[i] = w1[i];
        __syncthreads();
        float acc[4][4] = {};
        #pragma unroll 8
        for (int k = 0; k < H; k++) {
            float a0 = sV[(ty * 4 + 0) * 65 + k];
            float a1 = sV[(ty * 4 + 1) * 65 + k];
            float a2 = sV[(ty * 4 + 2) * 65 + k];
            float a3 = sV[(ty * 4 + 3) * 65 + k];
            float4 w4 = *(const float4*)&sW[k * H + tx * 4];
            acc[0][0] += a0 * w4.x; acc[0][1] += a0 * w4.y; acc[0][2] += a0 * w4.z; acc[0][3] += a0 * w4.w;
            acc[1][0] += a1 * w4.x; acc[1][1] += a1 * w4.y; acc[1][2] += a1 * w4.z; acc[1][3] += a1 * w4.w;
            acc[2][0] += a2 * w4.x; acc[2][1] += a2 * w4.y; acc[2][2] += a2 * w4.z; acc[2][3] += a2 * w4.w;
            acc[3][0] += a3 * w4.x; acc[3][1] += a3 * w4.y; acc[3][2] += a3 * w4.z; acc[3][3] += a3 * w4.w;
        }
        __syncthreads();
        #pragma unroll
        for (int i = 0; i < 4; i++)
            #pragma unroll
            for (int j = 0; j < 4; j++) {
                float vbl = acc[i][j] + b1[tx * 4 + j];
                sV[(ty * 4 + i) * 65 + tx * 4 + j] = vbl > 0.f ? vbl : 0.f;
            }
        for (int i = t; i < H * H; i += 256) sW[i] = w2[i];
        __syncthreads();
        float acc2[4][4] = {};
        #pragma unroll 8
        for (int k = 0; k < H; k++) {
            float a0 = sV[(ty * 4 + 0) * 65 + k];
            float a1 = sV[(ty * 4 + 1) * 65 + k];
            float a2 = sV[(ty * 4 + 2) * 65 + k];
            float a3 = sV[(ty * 4 + 3) * 65 + k];
            float4 w4 = *(const float4*)&sW[k * H + tx * 4];
            acc2[0][0] += a0 * w4.x; acc2[0][1] += a0 * w4.y; acc2[0][2] += a0 * w4.z; acc2[0][3] += a0 * w4.w;
            acc2[1][0] += a1 * w4.x; acc2[1][1] += a1 * w4.y; acc2[1][2] += a1 * w4.z; acc2[1][3] += a1 * w4.w;
            acc2[2][0] += a2 * w4.x; acc2[2][1] += a2 * w4.y; acc2[2][2] += a2 * w4.z; acc2[2][3] += a2 * w4.w;
            acc2[3][0] += a3 * w4.x; acc2[3][1] += a3 * w4.y; acc2[3][2] += a3 * w4.z; acc2[3][3] += a3 * w4.w;
        }
        __syncthreads();
        #pragma unroll
        for (int i = 0; i < 4; i++)
            #pragma unroll
            for (int j = 0; j < 4; j++) {
                float vbl = acc2[i][j] + b2[tx * 4 + j];
                sV[(ty * 4 + i) * 65 + tx * 4 + j] = vbl > 0.f ? vbl : 0.f;
            }
        __syncthreads();
    }
    for (int i = t; i < 64 * H; i += 256) {
        int r = i >> 6, c = i & 63;
        if (r0 + r < rows) vn[(r0 + r) * H + c] = sV[r * 65 + c];
    }
}

// ---------------- host launch ----------------
extern "C" void kernel_launch(void* const* d_in, const int* in_sizes, int n_in,
                              void* d_out, int out_size) {
    const float* x  = (const float*)d_in[0];
    const int*   ei = (const int*)d_in[1];
    const int*   hb = (const int*)d_in[2];
    int base = (n_in >= 18) ? 5 : 4;
    const float* w_in     = (const float*)d_in[base + 0];
    const float* a_src_in = (const float*)d_in[base + 1];
    const float* a_dst_in = (const float*)d_in[base + 2];
    const float* b_in     = (const float*)d_in[base + 3];
    const float* w_l      = (const float*)d_in[base + 4];
    const float* a_src_l  = (const float*)d_in[base + 5];
    const float* a_dst_l  = (const float*)d_in[base + 6];
    const float* b_l      = (const float*)d_in[base + 7];
    const float* mw1      = (const float*)d_in[base + 8];
    const float* mb1      = (const float*)d_in[base + 9];
    const float* mw2      = (const float*)d_in[base + 10];
    const float* mb2      = (const float*)d_in[base + 11];
    const float* vne      = (const float*)d_in[base + 12];

    int N = in_sizes[0] / 3;
    int E = in_sizes[1] / 2;

    float *pas, *pad, *pad2, *pvn, *pvnagg, *puv, *pwc, *pcc, *pps;
    float4 *pxa, *pxa2, *pxa3;
    __half* ph;
    int *pdeg, *pst, *pen, *pcur, *pssrc, *ptotal;
    cudaGetSymbolAddress((void**)&ph, g_h);
    cudaGetSymbolAddress((void**)&pxa, g_xa);
    cudaGetSymbolAddress((void**)&pxa2, g_xa2);
    cudaGetSymbolAddress((void**)&pxa3, g_xa3);
    cudaGetSymbolAddress((void**)&pas, g_as);
    cudaGetSymbolAddress((void**)&pad, g_ad);
    cudaGetSymbolAddress((void**)&pad2, g_ad2);
    cudaGetSymbolAddress((void**)&pdeg, g_deg);
    cudaGetSymbolAddress((void**)&pst, g_st);
    cudaGetSymbolAddress((void**)&pen, g_en);
    cudaGetSymbolAddress((void**)&pcur, g_cur);
    cudaGetSymbolAddress((void**)&pssrc, g_ssrc);
    cudaGetSymbolAddress((void**)&ptotal, g_total);
    cudaGetSymbolAddress((void**)&pvn, g_vn);
    cudaGetSymbolAddress((void**)&pvnagg, g_vnagg);
    cudaGetSymbolAddress((void**)&puv, g_uv);
    cudaGetSymbolAddress((void**)&pwc, g_wc);
    cudaGetSymbolAddress((void**)&pcc, g_cc);
    cudaGetSymbolAddress((void**)&pps, g_ps);

    int nwarp_blocks = (N + 7) / 8;
    int gemm_blocks  = (N + 63) / 64;
    int quad_blocks  = (N + 63) / 64;
    int nblocks_node = (N + 255) / 256;
    int nblocks_edge = (E + 255) / 256;
    int setup_blocks = 71 + nblocks_node + nblocks_edge;

    // 0: setup
    k_setup<<<setup_blocks, 256>>>(x, ei, w_in, a_src_in, a_dst_in, b_in,
                                   w_l, a_src_l, a_dst_l,
                                   puv, pwc, pcc, pps,
                                   pvn, pvnagg, vne, pxa, pad, pdeg,
                                   ptotal, N, E, nblocks_node);
    // 1-2: CSR alloc + scatter
    k_alloc<<<nblocks_node, 256>>>(pdeg, pst, pen, pcur, ptotal, N);
    k_scatter<<<(E + 1023) / 1024, 256>>>(ei, pcur, pssrc, E);

    // 3: layer-in GAT -> xa2
    k_gat_in<<<quad_blocks, 256>>>(pxa, pad, pst, pen, pssrc,
                                   pps, pxa2, pad2, N);
    // 4: layer-0 GAT -> xa3 + rank-3 vnagg
    k_gat0<<<quad_blocks, 256>>>(pxa2, pad2, pst, pen, pssrc, hb,
                                 pxa3, pvnagg, N);
    // 5: fused vn update (rank-3 expand) + both MLPs
    k_vn_mlp2<<<(HNUM + 1 + 63) / 64, 256>>>(pvn, pvnagg, pwc, pcc, b_l,
                                             mw1, mb1, mw2, mb2, HNUM + 1);

    // 6: l=1 GEMM reconstructs out_l0 on the fly from xa3
    k_gemm64<<<gemm_blocks, 256>>>(pxa3, pwc, pcc, b_l,
                                   w_l + H * H, puv + 2 * H, puv + 3 * H,
                                   pvn, hb, ph, pas, pad, N);
    // 7: final layer-1 GAT -> d_out
    k_gat<<<nwarp_blocks, 256>>>((const __half2*)ph, pas, pad, pst, pen, pssrc,
                                 b_l + H, (float*)d_out, N);
}

// round 16
// speedup vs baseline: 1.3181x; 1.0608x over previous
#include <cuda_runtime.h>
#include <math.h>

#define H 64
#define HNUM 256
#define NMAX 100000
#define EMAX 1200000
#define NEG_SLOPE 0.2f
#define CAP 128

// ---------------- scratch (static device globals) ----------------
__device__ float4 g_xa[NMAX];               // {x0,x1,x2,as} per node (layer-in)
__device__ float4 g_xa2[NMAX];              // {agg3, as2} per node (layer-0 input)
__device__ float4 g_xa3[NMAX];              // {agg3_l0, bits(hb)} per node (layer-0 out)
__device__ float g_ad[NMAX];
__device__ float g_as[NMAX];                // reused for as1 in final layer
__device__ float g_ad2[NMAX];
__device__ int   g_deg[NMAX];
__device__ int   g_st[NMAX];
__device__ int   g_en[NMAX];
__device__ int   g_cur[NMAX];
__device__ int   g_total;
__device__ int   g_ssrc[EMAX];
__device__ float g_vn[(HNUM + 1) * H];      // init'd each call; consumed by vn_mlp2
__device__ float g_vnagg[HNUM * 4];         // per-block {sum agg3, count}
__device__ float g_vnw[HNUM * H];           // (vn_new[b]+ccb) @ W_l1  (64KB table)
__device__ float g_vnu[HNUM];               // (vn_new[b]+ccb) . u1
__device__ float g_vnv[HNUM];               // (vn_new[b]+ccb) . v1
__device__ float g_wc2[3 * H];              // Wc @ W_l1
__device__ float g_ps1[8];                  // pu3[3], pd3[3]
__device__ float g_uv[4 * H];
__device__ float g_wc[3 * H];               // W_in @ W_l0  (3x64)
__device__ float g_cc[H];                   // (b_in + vn_emb) @ W_l0
__device__ float g_ps[8];                   // folded l0 attention coeffs

// ---------------- setup ----------------
__global__ void k_setup(const float* __restrict__ x,
                        const int* __restrict__ ei,
                        const float* __restrict__ w_in,
                        const float* __restrict__ a_src_in,
                        const float* __restrict__ a_dst_in,
                        const float* __restrict__ b_in,
                        const float* __restrict__ w_l,
                        const float* __restrict__ a_src_l,
                        const float* __restrict__ a_dst_l,
                        float* __restrict__ uv,
                        float* __restrict__ wc, float* __restrict__ cc,
                        float* __restrict__ ps,
                        float* __restrict__ vn, float* __restrict__ vnagg,
                        const float* __restrict__ emb,
                        float4* __restrict__ xa, float* __restrict__ ad_,
                        int* __restrict__ deg,
                        int* total, int n, int E, int nblocks_node) {
    int b = blockIdx.x, t = threadIdx.x;
    if (b == 0) {
        if (t == 0) *total = 0;
        int l = t >> 7;
        int isdst = (t >> 6) & 1;
        int j = t & 63;
        const float* a = isdst ? (a_dst_l + l * H) : (a_src_l + l * H);
        const float* W = w_l + l * H * H;
        float s = 0.f;
        #pragma unroll 8
        for (int k = 0; k < H; k++) s += W[j * H + k] * a[k];
        uv[(l * 2 + isdst) * H + j] = s;
    } else if (b == 1) {
        __shared__ float sWc[3 * H];
        __shared__ float sCc[H];
        if (t < 192) {
            int i = t >> 6, j = t & 63;
            float s = 0.f;
            #pragma unroll 8
            for (int k = 0; k < H; k++) s += w_in[i * H + k] * w_l[k * H + j];
            sWc[t] = s;
            wc[t] = s;
        } else {
            int j = t - 192;
            float s = 0.f;
            #pragma unroll 8
            for (int k = 0; k < H; k++) s += (b_in[k] + emb[k]) * w_l[k * H + j];
            sCc[j] = s;
            cc[j] = s;
        }
        __syncthreads();
        if (t < 8) {
            int isdst = t >> 2, c = t & 3;
            const float* a = isdst ? a_dst_l : a_src_l;   // layer 0
            float s = 0.f;
            if (c < 3) {
                #pragma unroll 8
                for (int m = 0; m < H; m++) s += sWc[c * H + m] * a[m];
            } else {
                #pragma unroll 8
                for (int m = 0; m < H; m++) s += sCc[m] * a[m];
            }
            ps[isdst * 4 + c] = s;
        }
    } else if (b <= 66) {
        int i = (b - 2) * 256 + t;
        if (i < (HNUM + 1) * H) vn[i] = emb[i & (H - 1)];
    } else if (b <= 70) {
        int i = (b - 67) * 256 + t;
        if (i < HNUM * 4) vnagg[i] = 0.f;
    } else if (b <= 70 + nblocks_node) {
        __shared__ float swa[6];
        if (t < 6) {
            int i = t % 3;
            const float* av = (t >= 3) ? a_dst_in : a_src_in;
            float s2 = 0.f;
            #pragma unroll 8
            for (int k = 0; k < H; k++) s2 += w_in[i * H + k] * av[k];
            swa[t] = s2;
        }
        __syncthreads();
        int i = (b - 71) * 256 + t;
        if (i < n) {
            float x0 = x[3 * i], x1 = x[3 * i + 1], x2 = x[3 * i + 2];
            xa[i] = make_float4(x0, x1, x2,
                                x0 * swa[0] + x1 * swa[1] + x2 * swa[2]);
            ad_[i] = x0 * swa[3] + x1 * swa[4] + x2 * swa[5];
        }
    } else {
        int i = (b - 71 - nblocks_node) * 256 + t;
        if (i < E) atomicAdd(&deg[ei[E + i]], 1);
    }
}

// ---------------- CSR alloc + ILP-4 scatter ----------------
__global__ __launch_bounds__(256) void k_alloc(int* __restrict__ deg,
                                               int* __restrict__ st,
                                               int* __restrict__ en,
                                               int* __restrict__ cur,
                                               int* total, int n) {
    __shared__ int sWarp[8];
    __shared__ int sBase;
    int t = threadIdx.x, lane = t & 31, w = t >> 5;
    int i = blockIdx.x * 256 + t;
    int d = 0;
    if (i < n) { d = deg[i]; deg[i] = 0; }
    int x = d;
    #pragma unroll
    for (int o = 1; o < 32; o <<= 1) {
        int y = __shfl_up_sync(0xffffffffu, x, o);
        if (lane >= o) x += y;
    }
    if (lane == 31) sWarp[w] = x;
    __syncthreads();
    if (t == 0) {
        int s = 0;
        #pragma unroll
        for (int k = 0; k < 8; k++) { int v = sWarp[k]; sWarp[k] = s; s += v; }
        sBase = atomicAdd(total, s);
    }
    __syncthreads();
    int start = sBase + sWarp[w] + x - d;
    if (i < n) { st[i] = start; cur[i] = start; en[i] = start + d; }
}

__global__ void k_scatter(const int* __restrict__ ei, int* cur,
                          int* __restrict__ ssrc, int E) {
    int base = blockIdx.x * 1024 + threadIdx.x;
    #pragma unroll
    for (int k = 0; k < 4; k++) {
        int i = base + k * 256;
        if (i < E) {
            int s = ei[i], d = ei[E + i];
            int pos = atomicAdd(&cur[d], 1);
            ssrc[pos] = s;
        }
    }
}

// ---------------- layer-in GAT, QUAD-PER-NODE online softmax -> xa2 pack ----------
__global__ __launch_bounds__(256) void k_gat_in(
    const float4* __restrict__ xa,
    const float* __restrict__ ad_,
    const int* __restrict__ st, const int* __restrict__ en,
    const int* __restrict__ ssrc,
    const float* __restrict__ ps,
    float4* __restrict__ xa2, float* __restrict__ ad2, int n) {
    __shared__ float sP[8];
    int t = threadIdx.x;
    if (t < 8) sP[t] = ps[t];
    __syncthreads();
    int node = blockIdx.x * 64 + (t >> 2);
    int sub  = t & 3;
    if (node >= n) return;
    int s0 = st[node], e0 = en[node];
    float adn = ad_[node];

    float m, den, a0, a1, a2;
    if (sub == 0) {
        float4 xs = xa[node];
        float aself = xs.w + adn;
        aself = aself > 0.f ? aself : NEG_SLOPE * aself;
        m = aself; den = 1.f;
        a0 = xs.x; a1 = xs.y; a2 = xs.z;
    } else {
        m = -INFINITY; den = 0.f; a0 = a1 = a2 = 0.f;
    }

    for (int e = s0 + sub; e < e0; e += 4) {
        int s = ssrc[e];
        float4 v = xa[s];
        float a = v.w + adn;
        a = a > 0.f ? a : NEG_SLOPE * a;
        float newm = fmaxf(m, a);
        float sc = (m >= newm) ? 1.f : __expf(m - newm);
        float ex = __expf(a - newm);
        den = den * sc + ex;
        a0  = a0  * sc + ex * v.x;
        a1  = a1  * sc + ex * v.y;
        a2  = a2  * sc + ex * v.z;
        m = newm;
    }

    #pragma unroll
    for (int off = 1; off <= 2; off <<= 1) {
        float om   = __shfl_xor_sync(0xffffffffu, m,   off);
        float oden = __shfl_xor_sync(0xffffffffu, den, off);
        float oa0  = __shfl_xor_sync(0xffffffffu, a0,  off);
        float oa1  = __shfl_xor_sync(0xffffffffu, a1,  off);
        float oa2  = __shfl_xor_sync(0xffffffffu, a2,  off);
        float newm = fmaxf(m, om);
        float sc  = (m  >= newm) ? 1.f : __expf(m  - newm);
        float osc = (om >= newm) ? 1.f : __expf(om - newm);
        den = den * sc + oden * osc;
        a0  = a0  * sc + oa0  * osc;
        a1  = a1  * sc + oa1  * osc;
        a2  = a2  * sc + oa2  * osc;
        m = newm;
    }

    if (sub == 0) {
        float inv = 1.f / den;
        a0 *= inv; a1 *= inv; a2 *= inv;
        xa2[node] = make_float4(a0, a1, a2,
                                a0 * sP[0] + a1 * sP[1] + a2 * sP[2] + sP[3]);
        ad2[node] = a0 * sP[4] + a1 * sP[5] + a2 * sP[6] + sP[7];
    }
}

// ---------------- layer-0 GAT, QUAD-PER-NODE on xa2 -> xa3 {agg3, hb} + vnagg ----------
__global__ __launch_bounds__(256) void k_gat0(
    const float4* __restrict__ xa2,
    const float* __restrict__ ad2,
    const int* __restrict__ st, const int* __restrict__ en,
    const int* __restrict__ ssrc,
    const int* __restrict__ hb,
    float4* __restrict__ xa3, float* __restrict__ vnagg, int n) {
    int t = threadIdx.x;
    int node = blockIdx.x * 64 + (t >> 2);
    int sub  = t & 3;
    if (node >= n) return;
    int s0 = st[node], e0 = en[node];
    float adn = ad2[node];

    float m, den, a0, a1, a2;
    if (sub == 0) {
        float4 xs = xa2[node];
        float aself = xs.w + adn;
        aself = aself > 0.f ? aself : NEG_SLOPE * aself;
        m = aself; den = 1.f;
        a0 = xs.x; a1 = xs.y; a2 = xs.z;
    } else {
        m = -INFINITY; den = 0.f; a0 = a1 = a2 = 0.f;
    }

    for (int e = s0 + sub; e < e0; e += 4) {
        int s = ssrc[e];
        float4 v = xa2[s];
        float a = v.w + adn;
        a = a > 0.f ? a : NEG_SLOPE * a;
        float newm = fmaxf(m, a);
        float sc = (m >= newm) ? 1.f : __expf(m - newm);
        float ex = __expf(a - newm);
        den = den * sc + ex;
        a0  = a0  * sc + ex * v.x;
        a1  = a1  * sc + ex * v.y;
        a2  = a2  * sc + ex * v.z;
        m = newm;
    }

    #pragma unroll
    for (int off = 1; off <= 2; off <<= 1) {
        float om   = __shfl_xor_sync(0xffffffffu, m,   off);
        float oden = __shfl_xor_sync(0xffffffffu, den, off);
        float oa0  = __shfl_xor_sync(0xffffffffu, a0,  off);
        float oa1  = __shfl_xor_sync(0xffffffffu, a1,  off);
        float oa2  = __shfl_xor_sync(0xffffffffu, a2,  off);
        float newm = fmaxf(m, om);
        float sc  = (m  >= newm) ? 1.f : __expf(m  - newm);
        float osc = (om >= newm) ? 1.f : __expf(om - newm);
        den = den * sc + oden * osc;
        a0  = a0  * sc + oa0  * osc;
        a1  = a1  * sc + oa1  * osc;
        a2  = a2  * sc + oa2  * osc;
        m = newm;
    }

    if (sub == 0) {
        float inv = 1.f / den;
        a0 *= inv; a1 *= inv; a2 *= inv;
        int blk = hb[node];
        xa3[node] = make_float4(a0, a1, a2, __int_as_float(blk));
        atomicAdd(&vnagg[blk * 4 + 0], a0);
        atomicAdd(&vnagg[blk * 4 + 1], a1);
        atomicAdd(&vnagg[blk * 4 + 2], a2);
        atomicAdd(&vnagg[blk * 4 + 3], 1.f);
    }
}

// ---------------- vn update (rank-3 expand) + MLPs + layer-1 folding epilogue ----------
// After the MLPs, each block also emits: vnW[b] = (vn_new[b]+ccb)@W_l1 (64KB table),
// vnu/vnv[b] = (vn_new[b]+ccb).{u1,v1}; block 0 emits Wc2 = Wc@W_l1 and pu3/pd3.
__global__ __launch_bounds__(256) void k_vn_mlp2(
    float* vn, const float* __restrict__ vnagg,
    const float* __restrict__ wc, const float* __restrict__ cc,
    const float* __restrict__ bias0,
    const float* __restrict__ mw1, const float* __restrict__ mb1,
    const float* __restrict__ mw2, const float* __restrict__ mb2,
    const float* __restrict__ w_l1, const float* __restrict__ uv,
    float* __restrict__ vnw, float* __restrict__ vnu, float* __restrict__ vnv,
    float* __restrict__ wc2, float* __restrict__ ps1, int rows) {
    __shared__ __align__(16) float sW[H * H];
    __shared__ float sV[64 * 65];
    __shared__ float sRoot[H];
    __shared__ float sColNew[H];
    __shared__ float red[4][H];
    __shared__ float sWc[3 * H];
    __shared__ float sCcB[H];
    __shared__ float sAg[64 * 4];
    int t = threadIdx.x;
    int r0 = blockIdx.x * 64;

    if (t < H) sRoot[t] = vn[HNUM * H + t];
    if (t < 192) sWc[t] = wc[t];
    if (t >= 192 && t < 256) sCcB[t - 192] = cc[t - 192] + bias0[t - 192];
    {
        int idx = r0 * 4 + t;
        sAg[t] = (idx < HNUM * 4) ? vnagg[idx] : 0.f;
    }
    __syncthreads();
    {
        int c = t & 63, g = t >> 6;
        float svn = 0.f, s0 = 0.f, s1 = 0.f, s2 = 0.f, s3 = 0.f;
        for (int r = g; r < HNUM; r += 4) {
            svn += vn[r * H + c];
            s0 += vnagg[r * 4];
            s1 += vnagg[r * 4 + 1];
            s2 += vnagg[r * 4 + 2];
            s3 += vnagg[r * 4 + 3];
        }
        red[g][c] = svn + s0 * sWc[c] + s1 * sWc[H + c] + s2 * sWc[2 * H + c] + s3 * sCcB[c];
    }
    __syncthreads();
    if (t < H) sColNew[t] = red[0][t] + red[1][t] + red[2][t] + red[3][t] + 257.f * sRoot[t];
    __syncthreads();
    for (int i = t; i < 64 * H; i += 256) {
        int r = i >> 6, c = i & 63;
        int gr = r0 + r;
        float val = 0.f;
        if (gr < HNUM) {
            float rec = sAg[r * 4] * sWc[c] + sAg[r * 4 + 1] * sWc[H + c]
                      + sAg[r * 4 + 2] * sWc[2 * H + c] + sAg[r * 4 + 3] * sCcB[c];
            val = vn[gr * H + c] + rec + sRoot[c];
        } else if (gr == HNUM) val = sColNew[c];
        sV[r * 65 + c] = val;
    }
    int ty = t >> 4, tx = t & 15;
    for (int m = 0; m < 2; m++) {
        const float* w1 = mw1 + m * H * H;
        const float* b1 = mb1 + m * H;
        const float* w2 = mw2 + m * H * H;
        const float* b2 = mb2 + m * H;
        for (int i = t; i < H * H; i += 256) sW[i] = w1[i];
        __syncthreads();
        float acc[4][4] = {};
        #pragma unroll 8
        for (int k = 0; k < H; k++) {
            float a0 = sV[(ty * 4 + 0) * 65 + k];
            float a1 = sV[(ty * 4 + 1) * 65 + k];
            float a2 = sV[(ty * 4 + 2) * 65 + k];
            float a3 = sV[(ty * 4 + 3) * 65 + k];
            float4 w4 = *(const float4*)&sW[k * H + tx * 4];
            acc[0][0] += a0 * w4.x; acc[0][1] += a0 * w4.y; acc[0][2] += a0 * w4.z; acc[0][3] += a0 * w4.w;
            acc[1][0] += a1 * w4.x; acc[1][1] += a1 * w4.y; acc[1][2] += a1 * w4.z; acc[1][3] += a1 * w4.w;
            acc[2][0] += a2 * w4.x; acc[2][1] += a2 * w4.y; acc[2][2] += a2 * w4.z; acc[2][3] += a2 * w4.w;
            acc[3][0] += a3 * w4.x; acc[3][1] += a3 * w4.y; acc[3][2] += a3 * w4.z; acc[3][3] += a3 * w4.w;
        }
        __syncthreads();
        #pragma unroll
        for (int i = 0; i < 4; i++)
            #pragma unroll
            for (int j = 0; j < 4; j++) {
                float vbl = acc[i][j] + b1[tx * 4 + j];
                sV[(ty * 4 + i) * 65 + tx * 4 + j] = vbl > 0.f ? vbl : 0.f;
            }
        for (int i = t; i < H * H; i += 256) sW[i] = w2[i];
        __syncthreads();
        float acc2[4][4] = {};
        #pragma unroll 8
        for (int k = 0; k < H; k++) {
            float a0 = sV[(ty * 4 + 0) * 65 + k];
            float a1 = sV[(ty * 4 + 1) * 65 + k];
            float a2 = sV[(ty * 4 + 2) * 65 + k];
            float a3 = sV[(ty * 4 + 3) * 65 + k];
            float4 w4 = *(const float4*)&sW[k * H + tx * 4];
            acc2[0][0] += a0 * w4.x; acc2[0][1] += a0 * w4.y; acc2[0][2] += a0 * w4.z; acc2[0][3] += a0 * w4.w;
            acc2[1][0] += a1 * w4.x; acc2[1][1] += a1 * w4.y; acc2[1][2] += a1 * w4.z; acc2[1][3] += a1 * w4.w;
            acc2[2][0] += a2 * w4.x; acc2[2][1] += a2 * w4.y; acc2[2][2] += a2 * w4.z; acc2[2][3] += a2 * w4.w;
            acc2[3][0] += a3 * w4.x; acc2[3][1] += a3 * w4.y; acc2[3][2] += a3 * w4.z; acc2[3][3] += a3 * w4.w;
        }
        __syncthreads();
        #pragma unroll
        for (int i = 0; i < 4; i++)
            #pragma unroll
            for (int j = 0; j < 4; j++) {
                float vbl = acc2[i][j] + b2[tx * 4 + j];
                sV[(ty * 4 + i) * 65 + tx * 4 + j] = vbl > 0.f ? vbl : 0.f;
            }
        __syncthreads();
    }
    // ---- layer-1 folding epilogue ----
    // add ccb to each direct row in-place (rows with gr >= HNUM unused below)
    for (int i = t; i < 64 * H; i += 256) {
        int r = i >> 6, c = i & 63;
        sV[r * 65 + c] += sCcB[c];
    }
    for (int i = t; i < H * H; i += 256) sW[i] = w_l1[i];
    __syncthreads();
    // vnW = rows @ W_l1
    {
        float acc[4][4] = {};
        #pragma unroll 8
        for (int k = 0; k < H; k++) {
            float a0 = sV[(ty * 4 + 0) * 65 + k];
            float a1 = sV[(ty * 4 + 1) * 65 + k];
            float a2 = sV[(ty * 4 + 2) * 65 + k];
            float a3 = sV[(ty * 4 + 3) * 65 + k];
            float4 w4 = *(const float4*)&sW[k * H + tx * 4];
            acc[0][0] += a0 * w4.x; acc[0][1] += a0 * w4.y; acc[0][2] += a0 * w4.z; acc[0][3] += a0 * w4.w;
            acc[1][0] += a1 * w4.x; acc[1][1] += a1 * w4.y; acc[1][2] += a1 * w4.z; acc[1][3] += a1 * w4.w;
            acc[2][0] += a2 * w4.x; acc[2][1] += a2 * w4.y; acc[2][2] += a2 * w4.z; acc[2][3] += a2 * w4.w;
            acc[3][0] += a3 * w4.x; acc[3][1] += a3 * w4.y; acc[3][2] += a3 * w4.z; acc[3][3] += a3 * w4.w;
        }
        #pragma unroll
        for (int i = 0; i < 4; i++) {
            int gr = r0 + ty * 4 + i;
            if (gr < HNUM) {
                float4 o4 = make_float4(acc[i][0], acc[i][1], acc[i][2], acc[i][3]);
                *(float4*)&vnw[gr * H + tx * 4] = o4;
            }
        }
    }
    // vnu/vnv per row
    if (t < 64) {
        int gr = r0 + t;
        if (gr < HNUM) {
            float su = 0.f, sv = 0.f;
            #pragma unroll 8
            for (int k = 0; k < H; k++) {
                float a = sV[t * 65 + k];
                su += a * uv[2 * H + k];
                sv += a * uv[3 * H + k];
            }
            vnu[gr] = su;
            vnv[gr] = sv;
        }
    }
    // block 0: Wc2 = Wc @ W_l1 (uses sW = W_l1), pu3/pd3 = Wc @ u1/v1
    if (blockIdx.x == 0) {
        if (t < 192) {
            int i = t >> 6, j = t & 63;
            float s = 0.f;
            #pragma unroll 8
            for (int k = 0; k < H; k++) s += sWc[i * H + k] * sW[k * H + j];
            wc2[t] = s;
        }
        if (t >= 192 && t < 198) {
            int q = t - 192;            // 0..5
            int isdst = q / 3, c = q % 3;
            const float* a = uv + (2 + isdst) * H;
            float s = 0.f;
            #pragma unroll 8
            for (int m = 0; m < H; m++) s += sWc[c * H + m] * a[m];
            ps1[isdst * 3 + c] = s;
        }
    }
}

// ---------------- prep1: per-node as1/ad1 from rank-3 + tables ----------------
__global__ void k_prep1(const float4* __restrict__ xa3,
                        const float* __restrict__ vnu, const float* __restrict__ vnv,
                        const float* __restrict__ ps1,
                        float* __restrict__ as1, float* __restrict__ ad1, int n) {
    __shared__ float sP[6];
    int t = threadIdx.x;
    if (t < 6) sP[t] = ps1[t];
    __syncthreads();
    int i = blockIdx.x * 256 + t;
    if (i >= n) return;
    float4 g = xa3[i];
    int hb = __float_as_int(g.w);
    as1[i] = g.x * sP[0] + g.y * sP[1] + g.z * sP[2] + vnu[hb];
    ad1[i] = g.x * sP[3] + g.y * sP[4] + g.z * sP[5] + vnv[hb];
}

// ---------------- final GAT: rank-3 + L1-resident vnW table gather ----------------
__global__ __launch_bounds__(256) void k_gat1(
    const float4* __restrict__ xa3,
    const float* __restrict__ as_, const float* __restrict__ ad_,
    const int* __restrict__ st, const int* __restrict__ en,
    const int* __restrict__ ssrc,
    const float2* __restrict__ vnw2,
    const float* __restrict__ wc2,
    const float* __restrict__ bias,
    float* __restrict__ out, int n) {
    __shared__ int   s_src[8][CAP];
    __shared__ float s_w[8][CAP];
    __shared__ float sWc2[3 * H];
    int t = threadIdx.x, lane = t & 31, w = t >> 5;
    if (t < 192) sWc2[t] = wc2[t];
    __syncthreads();
    int node = blockIdx.x * 8 + w;
    if (node >= n) return;
    int start = st[node], end = en[node];
    int deg = end - start;
    float adn = ad_[node];
    float aself = as_[node] + adn;
    aself = aself > 0.f ? aself : NEG_SLOPE * aself;
    float4 xhs = xa3[node];
    float2 acc;                    // per-lane 2 features of the vnW part
    float r0, r1, r2;              // rank-3 part (lane-redundant)
    float den;

    if (deg <= CAP) {
        float m = aself;
        for (int i = lane; i < deg; i += 32) {
            int s = ssrc[start + i];
            float a = as_[s] + adn;
            a = a > 0.f ? a : NEG_SLOPE * a;
            s_src[w][i] = s;
            s_w[w][i] = a;
            m = fmaxf(m, a);
        }
        #pragma unroll
        for (int o = 16; o; o >>= 1) m = fmaxf(m, __shfl_xor_sync(0xffffffffu, m, o));
        float wself = __expf(aself - m);
        den = (lane == 0) ? wself : 0.f;
        {
            int hbs = __float_as_int(xhs.w);
            float2 vw = vnw2[hbs * 32 + lane];
            acc.x = wself * vw.x;
            acc.y = wself * vw.y;
            r0 = wself * xhs.x; r1 = wself * xhs.y; r2 = wself * xhs.z;
        }
        for (int i = lane; i < deg; i += 32) {
            float ex = __expf(s_w[w][i] - m);
            s_w[w][i] = ex;
            den += ex;
        }
        #pragma unroll
        for (int o = 16; o; o >>= 1) den += __shfl_xor_sync(0xffffffffu, den, o);
        __syncwarp();
        for (int j = 0; j < deg; j++) {
            float wj = s_w[w][j];
            float4 xh = xa3[s_src[w][j]];
            int hbj = __float_as_int(xh.w);
            float2 vw = vnw2[hbj * 32 + lane];
            acc.x += wj * vw.x;
            acc.y += wj * vw.y;
            r0 += wj * xh.x; r1 += wj * xh.y; r2 += wj * xh.z;
        }
    } else {
        float m = aself;
        for (int e = start + lane; e < end; e += 32) {
            float a = as_[ssrc[e]] + adn;
            a = a > 0.f ? a : NEG_SLOPE * a;
            m = fmaxf(m, a);
        }
        #pragma unroll
        for (int o = 16; o; o >>= 1) m = fmaxf(m, __shfl_xor_sync(0xffffffffu, m, o));
        float wself = __expf(aself - m);
        float denl = (lane == 0) ? wself : 0.f;
        {
            int hbs = __float_as_int(xhs.w);
            float2 vw = vnw2[hbs * 32 + lane];
            acc.x = wself * vw.x;
            acc.y = wself * vw.y;
            r0 = wself * xhs.x; r1 = wself * xhs.y; r2 = wself * xhs.z;
        }
        for (int eb = start; eb < end; eb += 32) {
            int e = eb + lane;
            float ex = 0.f; int s = 0;
            if (e < end) {
                s = ssrc[e];
                float a = as_[s] + adn;
                a = a > 0.f ? a : NEG_SLOPE * a;
                ex = __expf(a - m);
            }
            denl += ex;
            int cnt = min(32, end - eb);
            for (int j = 0; j < cnt; j++) {
                float wj = __shfl_sync(0xffffffffu, ex, j);
                int sj   = __shfl_sync(0xffffffffu, s, j);
                float4 xh = xa3[sj];
                int hbj = __float_as_int(xh.w);
                float2 vw = vnw2[hbj * 32 + lane];
                acc.x += wj * vw.x;
                acc.y += wj * vw.y;
                r0 += wj * xh.x; r1 += wj * xh.y; r2 += wj * xh.z;
            }
        }
        den = denl;
        #pragma unroll
        for (int o = 16; o; o >>= 1) den += __shfl_xor_sync(0xffffffffu, den, o);
    }

    float inv = 1.f / den;
    float2 b = ((const float2*)bias)[lane];
    int c0 = lane * 2, c1 = c0 + 1;
    float o0 = (r0 * sWc2[c0] + r1 * sWc2[H + c0] + r2 * sWc2[2 * H + c0] + acc.x) * inv + b.x;
    float o1 = (r0 * sWc2[c1] + r1 * sWc2[H + c1] + r2 * sWc2[2 * H + c1] + acc.y) * inv + b.y;
    ((float2*)out)[(size_t)node * 32 + lane] = make_float2(o0, o1);
}

// ---------------- host launch ----------------
extern "C" void kernel_launch(void* const* d_in, const int* in_sizes, int n_in,
                              void* d_out, int out_size) {
    const float* x  = (const float*)d_in[0];
    const int*   ei = (const int*)d_in[1];
    const int*   hb = (const int*)d_in[2];
    int base = (n_in >= 18) ? 5 : 4;
    const float* w_in     = (const float*)d_in[base + 0];
    const float* a_src_in = (const float*)d_in[base + 1];
    const float* a_dst_in = (const float*)d_in[base + 2];
    const float* b_in     = (const float*)d_in[base + 3];
    const float* w_l      = (const float*)d_in[base + 4];
    const float* a_src_l  = (const float*)d_in[base + 5];
    const float* a_dst_l  = (const float*)d_in[base + 6];
    const float* b_l      = (const float*)d_in[base + 7];
    const float* mw1      = (const float*)d_in[base + 8];
    const float* mb1      = (const float*)d_in[base + 9];
    const float* mw2      = (const float*)d_in[base + 10];
    const float* mb2      = (const float*)d_in[base + 11];
    const float* vne      = (const float*)d_in[base + 12];

    int N = in_sizes[0] / 3;
    int E = in_sizes[1] / 2;

    float *pas, *pad, *pad2, *pvn, *pvnagg, *pvnw, *pvnu, *pvnv;
    float *puv, *pwc, *pcc, *pps, *pwc2, *pps1;
    float4 *pxa, *pxa2, *pxa3;
    int *pdeg, *pst, *pen, *pcur, *pssrc, *ptotal;
    cudaGetSymbolAddress((void**)&pxa, g_xa);
    cudaGetSymbolAddress((void**)&pxa2, g_xa2);
    cudaGetSymbolAddress((void**)&pxa3, g_xa3);
    cudaGetSymbolAddress((void**)&pas, g_as);
    cudaGetSymbolAddress((void**)&pad, g_ad);
    cudaGetSymbolAddress((void**)&pad2, g_ad2);
    cudaGetSymbolAddress((void**)&pdeg, g_deg);
    cudaGetSymbolAddress((void**)&pst, g_st);
    cudaGetSymbolAddress((void**)&pen, g_en);
    cudaGetSymbolAddress((void**)&pcur, g_cur);
    cudaGetSymbolAddress((void**)&pssrc, g_ssrc);
    cudaGetSymbolAddress((void**)&ptotal, g_total);
    cudaGetSymbolAddress((void**)&pvn, g_vn);
    cudaGetSymbolAddress((void**)&pvnagg, g_vnagg);
    cudaGetSymbolAddress((void**)&pvnw, g_vnw);
    cudaGetSymbolAddress((void**)&pvnu, g_vnu);
    cudaGetSymbolAddress((void**)&pvnv, g_vnv);
    cudaGetSymbolAddress((void**)&puv, g_uv);
    cudaGetSymbolAddress((void**)&pwc, g_wc);
    cudaGetSymbolAddress((void**)&pcc, g_cc);
    cudaGetSymbolAddress((void**)&pps, g_ps);
    cudaGetSymbolAddress((void**)&pwc2, g_wc2);
    cudaGetSymbolAddress((void**)&pps1, g_ps1);

    int nwarp_blocks = (N + 7) / 8;
    int quad_blocks  = (N + 63) / 64;
    int nblocks_node = (N + 255) / 256;
    int nblocks_edge = (E + 255) / 256;
    int setup_blocks = 71 + nblocks_node + nblocks_edge;

    // 0: setup
    k_setup<<<setup_blocks, 256>>>(x, ei, w_in, a_src_in, a_dst_in, b_in,
                                   w_l, a_src_l, a_dst_l,
                                   puv, pwc, pcc, pps,
                                   pvn, pvnagg, vne, pxa, pad, pdeg,
                                   ptotal, N, E, nblocks_node);
    // 1-2: CSR alloc + scatter
    k_alloc<<<nblocks_node, 256>>>(pdeg, pst, pen, pcur, ptotal, N);
    k_scatter<<<(E + 1023) / 1024, 256>>>(ei, pcur, pssrc, E);

    // 3: layer-in GAT -> xa2
    k_gat_in<<<quad_blocks, 256>>>(pxa, pad, pst, pen, pssrc,
                                   pps, pxa2, pad2, N);
    // 4: layer-0 GAT -> xa3 {agg3, hb} + rank-3 vnagg
    k_gat0<<<quad_blocks, 256>>>(pxa2, pad2, pst, pen, pssrc, hb,
                                 pxa3, pvnagg, N);
    // 5: vn update + MLPs + layer-1 fold (vnW/vnu/vnv/Wc2/ps1)
    k_vn_mlp2<<<(HNUM + 1 + 63) / 64, 256>>>(pvn, pvnagg, pwc, pcc, b_l,
                                             mw1, mb1, mw2, mb2,
                                             w_l + H * H, puv,
                                             pvnw, pvnu, pvnv, pwc2, pps1,
                                             HNUM + 1);
    // 6: per-node as1/ad1
    k_prep1<<<nblocks_node, 256>>>(pxa3, pvnu, pvnv, pps1, pas, pad, N);
    // 7: final GAT -> d_out (rank-3 + vnW table)
    k_gat1<<<nwarp_blocks, 256>>>(pxa3, pas, pad, pst, pen, pssrc,
                                  (const float2*)pvnw, pwc2, b_l + H,
                                  (float*)d_out, N);
}